// round 1
// baseline (speedup 1.0000x reference)
#include <cuda_runtime.h>
#include <cuda_bf16.h>

#define N_ROWS 16384
#define DIM    512
#define NNZ_E  163840
#define ITERS  10

// Scratch (static __device__ arrays — allocation-free per harness rules)
__device__ float g_buf0[N_ROWS * DIM];
__device__ float g_buf1[N_ROWS * DIM];
__device__ float g_sup[NNZ_E];
__device__ int   g_rowptr[N_ROWS + 1];
__device__ float g_invnorm[N_ROWS];
__device__ float g_invdenom[N_ROWS];
__device__ float g_scal[3];   // a = e^alpha, b = e^beta, k = 1/(4 s^2)

// ---------------------------------------------------------------------------
__global__ void k_scalars(const float* __restrict__ alpha,
                          const float* __restrict__ beta,
                          const float* __restrict__ sigma) {
    float a = expf(alpha[0]);
    float b = expf(beta[0]);
    float s = expf(sigma[0]);
    g_scal[0] = a;
    g_scal[1] = b;
    g_scal[2] = 1.0f / (4.0f * s * s);   // sim / (2 * (2 s^2))
}

// warp per row: inv L2 norm
__global__ void k_invnorm(const float* __restrict__ x) {
    int row  = (blockIdx.x * blockDim.x + threadIdx.x) >> 5;
    int lane = threadIdx.x & 31;
    if (row >= N_ROWS) return;
    const float4* xr = (const float4*)(x + (size_t)row * DIM);
    float s = 0.0f;
#pragma unroll
    for (int i = 0; i < 4; i++) {
        float4 v = xr[lane + 32 * i];
        s += v.x * v.x + v.y * v.y + v.z * v.z + v.w * v.w;
    }
#pragma unroll
    for (int o = 16; o; o >>= 1) s += __shfl_xor_sync(0xFFFFFFFFu, s, o);
    if (lane == 0) g_invnorm[row] = rsqrtf(fmaxf(s, 1e-12f));
}

// one thread per row (+1): CSR row pointers via lower_bound on sorted edge_row
__global__ void k_rowptr(const int* __restrict__ er) {
    int i = blockIdx.x * blockDim.x + threadIdx.x;
    if (i > N_ROWS) return;
    int lo = 0, hi = NNZ_E;
    while (lo < hi) {
        int mid = (lo + hi) >> 1;
        if (er[mid] < i) lo = mid + 1; else hi = mid;
    }
    g_rowptr[i] = lo;
}

// warp per row: sup[e] for all edges of the row + inv_denom[row]
__global__ void k_sup(const float* __restrict__ x,
                      const float* __restrict__ ev,
                      const int*   __restrict__ ec) {
    int row  = (blockIdx.x * blockDim.x + threadIdx.x) >> 5;
    int lane = threadIdx.x & 31;
    if (row >= N_ROWS) return;

    float a = g_scal[0], b = g_scal[1], k = g_scal[2];
    float inr = g_invnorm[row];

    const float4* xr = (const float4*)(x + (size_t)row * DIM);
    float4 r0 = xr[lane], r1 = xr[lane + 32], r2 = xr[lane + 64], r3 = xr[lane + 96];

    int e0 = g_rowptr[row], e1 = g_rowptr[row + 1];
    float nsum = 0.0f;

    for (int e = e0; e < e1; e++) {
        int col = ec[e];
        const float4* xc = (const float4*)(x + (size_t)col * DIM);
        float4 c0 = xc[lane], c1 = xc[lane + 32], c2 = xc[lane + 64], c3 = xc[lane + 96];
        float d = r0.x * c0.x + r0.y * c0.y + r0.z * c0.z + r0.w * c0.w;
        d += r1.x * c1.x + r1.y * c1.y + r1.z * c1.z + r1.w * c1.w;
        d += r2.x * c2.x + r2.y * c2.y + r2.z * c2.z + r2.w * c2.w;
        d += r3.x * c3.x + r3.y * c3.y + r3.z * c3.z + r3.w * c3.w;
#pragma unroll
        for (int o = 16; o; o >>= 1) d += __shfl_xor_sync(0xFFFFFFFFu, d, o);
        // diagonal: sim forced to 0 before exp -> factor 1
        float sim = (col == row) ? 0.0f : d * inr * g_invnorm[col];
        float sup = ev[e] * expf(sim * k);
        if (lane == 0) g_sup[e] = sup;
        nsum += sup;   // identical across lanes (xor reduce broadcasts)
    }
    if (lane == 0) g_invdenom[row] = 1.0f / (b + nsum * a + a);
}

// warp per row: one diffusion step  out = (x*b + (A@in + in)*a) / denom
__global__ void k_iter(const float* __restrict__ in,
                       const float* __restrict__ x,
                       float*       __restrict__ out,
                       const int*   __restrict__ ec) {
    int row  = (blockIdx.x * blockDim.x + threadIdx.x) >> 5;
    int lane = threadIdx.x & 31;
    if (row >= N_ROWS) return;

    float a = g_scal[0], b = g_scal[1];
    float idn = g_invdenom[row];
    int e0 = g_rowptr[row], e1 = g_rowptr[row + 1];

    float4 acc0 = {0, 0, 0, 0}, acc1 = {0, 0, 0, 0}, acc2 = {0, 0, 0, 0}, acc3 = {0, 0, 0, 0};

    for (int e = e0; e < e1; e++) {
        float w = g_sup[e];
        const float4* p = (const float4*)(in + (size_t)ec[e] * DIM);
        float4 v0 = p[lane], v1 = p[lane + 32], v2 = p[lane + 64], v3 = p[lane + 96];
        acc0.x += w * v0.x; acc0.y += w * v0.y; acc0.z += w * v0.z; acc0.w += w * v0.w;
        acc1.x += w * v1.x; acc1.y += w * v1.y; acc1.z += w * v1.z; acc1.w += w * v1.w;
        acc2.x += w * v2.x; acc2.y += w * v2.y; acc2.z += w * v2.z; acc2.w += w * v2.w;
        acc3.x += w * v3.x; acc3.y += w * v3.y; acc3.z += w * v3.z; acc3.w += w * v3.w;
    }

    const float4* pin = (const float4*)(in + (size_t)row * DIM);
    const float4* px  = (const float4*)(x  + (size_t)row * DIM);
    float4*       po  = (float4*)(out + (size_t)row * DIM);

#pragma unroll
    for (int i = 0; i < 4; i++) {
        float4 vi = pin[lane + 32 * i];
        float4 vx = px[lane + 32 * i];
        float4 va = (i == 0) ? acc0 : (i == 1) ? acc1 : (i == 2) ? acc2 : acc3;
        float4 o;
        o.x = (vx.x * b + (va.x + vi.x) * a) * idn;
        o.y = (vx.y * b + (va.y + vi.y) * a) * idn;
        o.z = (vx.z * b + (va.z + vi.z) * a) * idn;
        o.w = (vx.w * b + (va.w + vi.w) * a) * idn;
        po[lane + 32 * i] = o;
    }
}

// ---------------------------------------------------------------------------
extern "C" void kernel_launch(void* const* d_in, const int* in_sizes, int n_in,
                              void* d_out, int out_size) {
    const float* x     = (const float*)d_in[0];
    const float* alpha = (const float*)d_in[1];
    const float* beta  = (const float*)d_in[2];
    const float* sigma = (const float*)d_in[3];
    const float* ev    = (const float*)d_in[4];
    const int*   er    = (const int*)d_in[5];
    const int*   ec    = (const int*)d_in[6];
    float*       out   = (float*)d_out;

    float* b0 = nullptr; float* b1 = nullptr;
    cudaGetSymbolAddress((void**)&b0, g_buf0);
    cudaGetSymbolAddress((void**)&b1, g_buf1);

    const int TPB = 256;
    const int ROW_BLOCKS = (N_ROWS * 32) / TPB;   // warp per row

    k_scalars<<<1, 1>>>(alpha, beta, sigma);
    k_invnorm<<<ROW_BLOCKS, TPB>>>(x);
    k_rowptr<<<(N_ROWS + 1 + TPB - 1) / TPB, TPB>>>(er);
    k_sup<<<ROW_BLOCKS, TPB>>>(x, ev, ec);

    const float* in_ptr = x;
    for (int it = 0; it < ITERS; it++) {
        float* out_ptr = (it == ITERS - 1) ? out : ((it & 1) == 0 ? b0 : b1);
        k_iter<<<ROW_BLOCKS, TPB>>>(in_ptr, x, out_ptr, ec);
        in_ptr = out_ptr;
    }
}

// round 2
// speedup vs baseline: 1.0036x; 1.0036x over previous
#include <cuda_runtime.h>
#include <cuda_fp16.h>

#define N_ROWS 16384
#define DIM    512
#define NNZ_E  163840
#define ITERS  10

// Scratch (static __device__ arrays — allocation-free per harness rules)
__device__ float  g_buf0[N_ROWS * DIM];
__device__ float  g_buf1[N_ROWS * DIM];
__device__ __half g_h0[N_ROWS * DIM];
__device__ __half g_h1[N_ROWS * DIM];
__device__ __half g_xh[N_ROWS * DIM];
__device__ float  g_sup[NNZ_E];
__device__ int    g_rowptr[N_ROWS + 1];
__device__ float  g_invnorm[N_ROWS];
__device__ float  g_rowsum[N_ROWS];
__device__ float  g_invdenom[N_ROWS];
__device__ float  g_scal[3];   // a = e^alpha, b = e^beta, k = 1/(4 s^2)

// ---------------------------------------------------------------------------
__global__ void k_scalars(const float* __restrict__ alpha,
                          const float* __restrict__ beta,
                          const float* __restrict__ sigma) {
    float a = expf(alpha[0]);
    float b = expf(beta[0]);
    float s = expf(sigma[0]);
    g_scal[0] = a;
    g_scal[1] = b;
    g_scal[2] = 1.0f / (4.0f * s * s);
}

// warp per row: inv L2 norm + fp16 shadow copy of x
// Element partition per lane L: scalars [8L, 8L+8) and [8L+256, 8L+264).
__global__ void k_invnorm(const float* __restrict__ x) {
    int row  = (blockIdx.x * blockDim.x + threadIdx.x) >> 5;
    int lane = threadIdx.x & 31;
    if (row >= N_ROWS) return;

    const float4* xr = (const float4*)(x + (size_t)row * DIM);
    uint4* xh = (uint4*)(g_xh + (size_t)row * DIM);

    float s = 0.0f;
#pragma unroll
    for (int seg = 0; seg < 2; seg++) {
        float4 a = xr[2 * lane + 64 * seg];
        float4 b = xr[2 * lane + 1 + 64 * seg];
        s += a.x * a.x + a.y * a.y + a.z * a.z + a.w * a.w;
        s += b.x * b.x + b.y * b.y + b.z * b.z + b.w * b.w;
        __half2 h0 = __floats2half2_rn(a.x, a.y);
        __half2 h1 = __floats2half2_rn(a.z, a.w);
        __half2 h2 = __floats2half2_rn(b.x, b.y);
        __half2 h3 = __floats2half2_rn(b.z, b.w);
        uint4 u;
        u.x = *(unsigned*)&h0; u.y = *(unsigned*)&h1;
        u.z = *(unsigned*)&h2; u.w = *(unsigned*)&h3;
        xh[lane + 32 * seg] = u;
    }
#pragma unroll
    for (int o = 16; o; o >>= 1) s += __shfl_xor_sync(0xFFFFFFFFu, s, o);
    if (lane == 0) g_invnorm[row] = rsqrtf(fmaxf(s, 1e-12f));
}

// one thread per row (+1): CSR row pointers via lower_bound; also zero rowsum
__global__ void k_rowptr(const int* __restrict__ er) {
    int i = blockIdx.x * blockDim.x + threadIdx.x;
    if (i > N_ROWS) return;
    if (i < N_ROWS) g_rowsum[i] = 0.0f;
    int lo = 0, hi = NNZ_E;
    while (lo < hi) {
        int mid = (lo + hi) >> 1;
        if (er[mid] < i) lo = mid + 1; else hi = mid;
    }
    g_rowptr[i] = lo;
}

// warp per EDGE: sup[e] = ev[e] * exp(sim * k); atomic row sums
__global__ void k_sup(const float* __restrict__ x,
                      const float* __restrict__ ev,
                      const int*   __restrict__ er,
                      const int*   __restrict__ ec) {
    int e    = (blockIdx.x * blockDim.x + threadIdx.x) >> 5;
    int lane = threadIdx.x & 31;
    if (e >= NNZ_E) return;

    int row = er[e];
    int col = ec[e];
    const float4* xr = (const float4*)(x + (size_t)row * DIM);
    const float4* xc = (const float4*)(x + (size_t)col * DIM);

    float d = 0.0f;
#pragma unroll
    for (int i = 0; i < 4; i++) {
        float4 r = xr[lane + 32 * i];
        float4 c = xc[lane + 32 * i];
        d += r.x * c.x + r.y * c.y + r.z * c.z + r.w * c.w;
    }
#pragma unroll
    for (int o = 16; o; o >>= 1) d += __shfl_xor_sync(0xFFFFFFFFu, d, o);

    if (lane == 0) {
        float sim = (col == row) ? 0.0f : d * g_invnorm[row] * g_invnorm[col];
        float sup = ev[e] * expf(sim * g_scal[2]);
        g_sup[e] = sup;
        atomicAdd(&g_rowsum[row], sup);
    }
}

// thread per row: invdenom
__global__ void k_denom() {
    int i = blockIdx.x * blockDim.x + threadIdx.x;
    if (i >= N_ROWS) return;
    float a = g_scal[0], b = g_scal[1];
    g_invdenom[i] = 1.0f / (b + g_rowsum[i] * a + a);
}

// warp per row: one diffusion step.
// Gather from fp16 buffer; exact row term from fp32 buffer.
// Lane L owns scalars [8L, 8L+8) and [8L+256, 8L+264).
__global__ void k_iter(const float*  __restrict__ in_f,
                       const __half* __restrict__ in_h,
                       const float*  __restrict__ x,
                       float*        __restrict__ out_f,
                       __half*       __restrict__ out_h,
                       const int*    __restrict__ ec,
                       int write_half) {
    int row  = (blockIdx.x * blockDim.x + threadIdx.x) >> 5;
    int lane = threadIdx.x & 31;
    if (row >= N_ROWS) return;

    float a = g_scal[0], b = g_scal[1];
    float idn = g_invdenom[row];
    int e0 = g_rowptr[row], e1 = g_rowptr[row + 1];

    float acc[16];
#pragma unroll
    for (int i = 0; i < 16; i++) acc[i] = 0.0f;

    int   col_n = 0;
    float w_n   = 0.0f;
    if (e0 < e1) { col_n = ec[e0]; w_n = g_sup[e0]; }

    for (int e = e0; e < e1; e++) {
        int   col = col_n;
        float w   = w_n;
        if (e + 1 < e1) { col_n = ec[e + 1]; w_n = g_sup[e + 1]; }

        const uint4* p = (const uint4*)(in_h + (size_t)col * DIM);
        uint4 u0 = p[lane];
        uint4 u1 = p[lane + 32];

#pragma unroll
        for (int j = 0; j < 4; j++) {
            unsigned raw0 = (&u0.x)[j];
            unsigned raw1 = (&u1.x)[j];
            float2 f0 = __half22float2(*(__half2*)&raw0);
            float2 f1 = __half22float2(*(__half2*)&raw1);
            acc[2 * j    ] += w * f0.x;
            acc[2 * j + 1] += w * f0.y;
            acc[8 + 2 * j    ] += w * f1.x;
            acc[8 + 2 * j + 1] += w * f1.y;
        }
    }

    const float4* pin = (const float4*)(in_f + (size_t)row * DIM);
    const float4* px  = (const float4*)(x   + (size_t)row * DIM);
    float4*       po  = (float4*)(out_f + (size_t)row * DIM);
    uint4*        ph  = (uint4*)(out_h + (size_t)row * DIM);

#pragma unroll
    for (int seg = 0; seg < 2; seg++) {
        float res[8];
#pragma unroll
        for (int q = 0; q < 2; q++) {
            int fidx = 2 * lane + q + 64 * seg;
            float4 vi = pin[fidx];
            float4 vx = px[fidx];
            float4 o;
            o.x = (vx.x * b + (acc[8 * seg + 4 * q + 0] + vi.x) * a) * idn;
            o.y = (vx.y * b + (acc[8 * seg + 4 * q + 1] + vi.y) * a) * idn;
            o.z = (vx.z * b + (acc[8 * seg + 4 * q + 2] + vi.z) * a) * idn;
            o.w = (vx.w * b + (acc[8 * seg + 4 * q + 3] + vi.w) * a) * idn;
            po[fidx] = o;
            res[4 * q + 0] = o.x; res[4 * q + 1] = o.y;
            res[4 * q + 2] = o.z; res[4 * q + 3] = o.w;
        }
        if (write_half) {
            __half2 h0 = __floats2half2_rn(res[0], res[1]);
            __half2 h1 = __floats2half2_rn(res[2], res[3]);
            __half2 h2 = __floats2half2_rn(res[4], res[5]);
            __half2 h3 = __floats2half2_rn(res[6], res[7]);
            uint4 u;
            u.x = *(unsigned*)&h0; u.y = *(unsigned*)&h1;
            u.z = *(unsigned*)&h2; u.w = *(unsigned*)&h3;
            ph[lane + 32 * seg] = u;
        }
    }
}

// ---------------------------------------------------------------------------
extern "C" void kernel_launch(void* const* d_in, const int* in_sizes, int n_in,
                              void* d_out, int out_size) {
    const float* x     = (const float*)d_in[0];
    const float* alpha = (const float*)d_in[1];
    const float* beta  = (const float*)d_in[2];
    const float* sigma = (const float*)d_in[3];
    const float* ev    = (const float*)d_in[4];
    const int*   er    = (const int*)d_in[5];
    const int*   ec    = (const int*)d_in[6];
    float*       out   = (float*)d_out;

    float *b0, *b1; __half *h0, *h1, *xh;
    cudaGetSymbolAddress((void**)&b0, g_buf0);
    cudaGetSymbolAddress((void**)&b1, g_buf1);
    cudaGetSymbolAddress((void**)&h0, g_h0);
    cudaGetSymbolAddress((void**)&h1, g_h1);
    cudaGetSymbolAddress((void**)&xh, g_xh);

    const int TPB = 256;
    const int ROW_BLOCKS  = (N_ROWS * 32) / TPB;   // warp per row
    const int EDGE_BLOCKS = (NNZ_E  * 32) / TPB;   // warp per edge

    k_scalars<<<1, 1>>>(alpha, beta, sigma);
    k_invnorm<<<ROW_BLOCKS, TPB>>>(x);
    k_rowptr<<<(N_ROWS + 1 + TPB - 1) / TPB, TPB>>>(er);
    k_sup<<<EDGE_BLOCKS, TPB>>>(x, ev, er, ec);
    k_denom<<<N_ROWS / TPB, TPB>>>();

    const float*  in_f = x;
    const __half* in_h = xh;
    for (int it = 0; it < ITERS; it++) {
        int last = (it == ITERS - 1);
        float*  out_f = last ? out : ((it & 1) == 0 ? b0 : b1);
        __half* out_h = (it & 1) == 0 ? h0 : h1;
        k_iter<<<ROW_BLOCKS, TPB>>>(in_f, in_h, x, out_f, out_h, ec, !last);
        in_f = out_f;
        in_h = out_h;
    }
}

// round 3
// speedup vs baseline: 1.3061x; 1.3014x over previous
#include <cuda_runtime.h>
#include <cuda_fp16.h>

#define N_ROWS 16384
#define DIM    512
#define NNZ_E  163840
#define ITERS  10

// Scratch (static __device__ arrays — allocation-free per harness rules)
__device__ __align__(16) __half g_h0[N_ROWS * DIM];
__device__ __align__(16) __half g_h1[N_ROWS * DIM];
__device__ __align__(16) __half g_xh[N_ROWS * DIM];
__device__ int2  g_cw[NNZ_E];          // (col, weight-as-int) per edge
__device__ int   g_rowptr[N_ROWS + 1];
__device__ float g_invnorm[N_ROWS];
__device__ float g_rowsum[N_ROWS];
__device__ float g_invdenom[N_ROWS];
__device__ float g_scal[3];            // a = e^alpha, b = e^beta, k = 1/(4 s^2)

// ---------------------------------------------------------------------------
__global__ void k_scalars(const float* __restrict__ alpha,
                          const float* __restrict__ beta,
                          const float* __restrict__ sigma) {
    float a = expf(alpha[0]);
    float b = expf(beta[0]);
    float s = expf(sigma[0]);
    g_scal[0] = a;
    g_scal[1] = b;
    g_scal[2] = 1.0f / (4.0f * s * s);
}

// warp per row: inv L2 norm + fp16 shadow copy of x
__global__ void k_invnorm(const float* __restrict__ x) {
    int row  = (blockIdx.x * blockDim.x + threadIdx.x) >> 5;
    int lane = threadIdx.x & 31;
    if (row >= N_ROWS) return;

    const float4* xr = (const float4*)(x + (size_t)row * DIM);
    uint4* xh = (uint4*)(g_xh + (size_t)row * DIM);

    float s = 0.0f;
#pragma unroll
    for (int seg = 0; seg < 2; seg++) {
        float4 a = xr[2 * lane + 64 * seg];
        float4 b = xr[2 * lane + 1 + 64 * seg];
        s += a.x * a.x + a.y * a.y + a.z * a.z + a.w * a.w;
        s += b.x * b.x + b.y * b.y + b.z * b.z + b.w * b.w;
        __half2 h0 = __floats2half2_rn(a.x, a.y);
        __half2 h1 = __floats2half2_rn(a.z, a.w);
        __half2 h2 = __floats2half2_rn(b.x, b.y);
        __half2 h3 = __floats2half2_rn(b.z, b.w);
        uint4 u;
        u.x = *(unsigned*)&h0; u.y = *(unsigned*)&h1;
        u.z = *(unsigned*)&h2; u.w = *(unsigned*)&h3;
        xh[2 * lane + 32 * seg - lane] = u;   // = lane + 32*seg  (kept explicit below)
    }
#pragma unroll
    for (int o = 16; o; o >>= 1) s += __shfl_xor_sync(0xFFFFFFFFu, s, o);
    if (lane == 0) g_invnorm[row] = rsqrtf(fmaxf(s, 1e-12f));
}

// NOTE on k_invnorm layout: the fp16 shadow must be in natural element order.
// The expression above writes uint4 slot (lane + 32*seg) covering halfs
// [ (lane+32*seg)*8 , +8 ), while the fp32 source reads float4 slots 2*lane(+1)
// covering floats [8*lane, 8*lane+8). Those are the same scalars for seg=0;
// for seg=1 source floats are [8*lane+256, +8) and dest halfs are
// [ (lane+32)*8, +8 ) = [8*lane+256, +8).  Order is preserved.

// one thread per row (+1): CSR row pointers via lower_bound; also zero rowsum
__global__ void k_rowptr(const int* __restrict__ er) {
    int i = blockIdx.x * blockDim.x + threadIdx.x;
    if (i > N_ROWS) return;
    if (i < N_ROWS) g_rowsum[i] = 0.0f;
    int lo = 0, hi = NNZ_E;
    while (lo < hi) {
        int mid = (lo + hi) >> 1;
        if (er[mid] < i) lo = mid + 1; else hi = mid;
    }
    g_rowptr[i] = lo;
}

// warp per EDGE: fp16 dot -> sup; pack (col, sup) into g_cw; atomic row sums
__global__ void k_sup(const float* __restrict__ ev,
                      const int*   __restrict__ er,
                      const int*   __restrict__ ec) {
    int e    = (blockIdx.x * blockDim.x + threadIdx.x) >> 5;
    int lane = threadIdx.x & 31;
    if (e >= NNZ_E) return;

    int row = er[e];
    int col = ec[e];
    const uint4* xr = (const uint4*)(g_xh + (size_t)row * DIM);
    const uint4* xc = (const uint4*)(g_xh + (size_t)col * DIM);

    uint4 r0 = xr[lane], r1 = xr[lane + 32];
    uint4 c0 = xc[lane], c1 = xc[lane + 32];

    float d = 0.0f;
#pragma unroll
    for (int j = 0; j < 4; j++) {
        unsigned ra = (&r0.x)[j], rb = (&r1.x)[j];
        unsigned ca = (&c0.x)[j], cb = (&c1.x)[j];
        float2 fr0 = __half22float2(*(__half2*)&ra);
        float2 fr1 = __half22float2(*(__half2*)&rb);
        float2 fc0 = __half22float2(*(__half2*)&ca);
        float2 fc1 = __half22float2(*(__half2*)&cb);
        d += fr0.x * fc0.x + fr0.y * fc0.y;
        d += fr1.x * fc1.x + fr1.y * fc1.y;
    }
#pragma unroll
    for (int o = 16; o; o >>= 1) d += __shfl_xor_sync(0xFFFFFFFFu, d, o);

    if (lane == 0) {
        float sim = (col == row) ? 0.0f : d * g_invnorm[row] * g_invnorm[col];
        float sup = ev[e] * expf(sim * g_scal[2]);
        g_cw[e] = make_int2(col, __float_as_int(sup));
        atomicAdd(&g_rowsum[row], sup);
    }
}

// thread per row: invdenom
__global__ void k_denom() {
    int i = blockIdx.x * blockDim.x + threadIdx.x;
    if (i >= N_ROWS) return;
    float a = g_scal[0], b = g_scal[1];
    g_invdenom[i] = 1.0f / (b + g_rowsum[i] * a + a);
}

// warp per HALF-row: one diffusion step, fp16 state.
// gw = row*2 + half.  Lane owns halfs [half*256 + 8*lane, +8).
__global__ void k_iter(const __half* __restrict__ in_h,
                       const float*  __restrict__ x,
                       __half*       __restrict__ out_h,
                       float*        __restrict__ out_f,
                       int last) {
    int gw   = (blockIdx.x * blockDim.x + threadIdx.x) >> 5;
    int lane = threadIdx.x & 31;
    int row  = gw >> 1;
    int half = gw & 1;
    if (row >= N_ROWS) return;

    float a = g_scal[0], b = g_scal[1];
    float idn = g_invdenom[row];
    int e0 = g_rowptr[row], e1 = g_rowptr[row + 1];

    const __half* base = in_h + half * (DIM / 2);

    float acc[8];
#pragma unroll
    for (int i = 0; i < 8; i++) acc[i] = 0.0f;

    for (int e = e0; e < e1; e += 2) {
        int2 A = g_cw[e];
        int  has2 = (e + 1 < e1);
        int2 B = has2 ? g_cw[e + 1] : A;

        uint4 ua = ((const uint4*)(base + (size_t)A.x * DIM))[lane];
        uint4 ub = ((const uint4*)(base + (size_t)B.x * DIM))[lane];
        float wa = __int_as_float(A.y);
        float wb = has2 ? __int_as_float(B.y) : 0.0f;

#pragma unroll
        for (int j = 0; j < 4; j++) {
            unsigned rawa = (&ua.x)[j];
            unsigned rawb = (&ub.x)[j];
            float2 fa = __half22float2(*(__half2*)&rawa);
            float2 fb = __half22float2(*(__half2*)&rawb);
            acc[2 * j    ] += wa * fa.x + wb * fb.x;
            acc[2 * j + 1] += wa * fa.y + wb * fb.y;
        }
    }

    // row term (fp16 state) + x term (fp32 exact)
    size_t off = (size_t)row * DIM + half * (DIM / 2);
    uint4 ui = ((const uint4*)(in_h + off))[lane];
    const float4* px = (const float4*)(x + off);
    float4 vx0 = px[2 * lane];
    float4 vx1 = px[2 * lane + 1];

    float fi[8];
#pragma unroll
    for (int j = 0; j < 4; j++) {
        unsigned raw = (&ui.x)[j];
        float2 f = __half22float2(*(__half2*)&raw);
        fi[2 * j] = f.x; fi[2 * j + 1] = f.y;
    }

    float o[8];
    o[0] = (vx0.x * b + (acc[0] + fi[0]) * a) * idn;
    o[1] = (vx0.y * b + (acc[1] + fi[1]) * a) * idn;
    o[2] = (vx0.z * b + (acc[2] + fi[2]) * a) * idn;
    o[3] = (vx0.w * b + (acc[3] + fi[3]) * a) * idn;
    o[4] = (vx1.x * b + (acc[4] + fi[4]) * a) * idn;
    o[5] = (vx1.y * b + (acc[5] + fi[5]) * a) * idn;
    o[6] = (vx1.z * b + (acc[6] + fi[6]) * a) * idn;
    o[7] = (vx1.w * b + (acc[7] + fi[7]) * a) * idn;

    __half2 h0 = __floats2half2_rn(o[0], o[1]);
    __half2 h1 = __floats2half2_rn(o[2], o[3]);
    __half2 h2 = __floats2half2_rn(o[4], o[5]);
    __half2 h3 = __floats2half2_rn(o[6], o[7]);
    uint4 u;
    u.x = *(unsigned*)&h0; u.y = *(unsigned*)&h1;
    u.z = *(unsigned*)&h2; u.w = *(unsigned*)&h3;
    ((uint4*)(out_h + off))[lane] = u;

    if (last) {
        float4* po = (float4*)(out_f + off);
        po[2 * lane]     = make_float4(o[0], o[1], o[2], o[3]);
        po[2 * lane + 1] = make_float4(o[4], o[5], o[6], o[7]);
    }
}

// ---------------------------------------------------------------------------
extern "C" void kernel_launch(void* const* d_in, const int* in_sizes, int n_in,
                              void* d_out, int out_size) {
    const float* x     = (const float*)d_in[0];
    const float* alpha = (const float*)d_in[1];
    const float* beta  = (const float*)d_in[2];
    const float* sigma = (const float*)d_in[3];
    const float* ev    = (const float*)d_in[4];
    const int*   er    = (const int*)d_in[5];
    const int*   ec    = (const int*)d_in[6];
    float*       out   = (float*)d_out;

    __half *h0, *h1, *xh;
    cudaGetSymbolAddress((void**)&h0, g_h0);
    cudaGetSymbolAddress((void**)&h1, g_h1);
    cudaGetSymbolAddress((void**)&xh, g_xh);

    const int TPB = 256;
    const int ROW_BLOCKS  = (N_ROWS * 32) / TPB;       // warp per row
    const int HALF_BLOCKS = (N_ROWS * 2 * 32) / TPB;   // warp per half-row
    const int EDGE_BLOCKS = (NNZ_E * 32) / TPB;        // warp per edge

    k_scalars<<<1, 1>>>(alpha, beta, sigma);
    k_invnorm<<<ROW_BLOCKS, TPB>>>(x);
    k_rowptr<<<(N_ROWS + 1 + TPB - 1) / TPB, TPB>>>(er);
    k_sup<<<EDGE_BLOCKS, TPB>>>(ev, er, ec);
    k_denom<<<N_ROWS / TPB, TPB>>>();

    const __half* in_h = xh;
    for (int it = 0; it < ITERS; it++) {
        int last = (it == ITERS - 1);
        __half* out_h = (it & 1) == 0 ? h0 : h1;
        k_iter<<<HALF_BLOCKS, TPB>>>(in_h, x, out_h, out, last);
        in_h = out_h;
    }
}